// round 5
// baseline (speedup 1.0000x reference)
#include <cuda_runtime.h>
#include <cuda_bf16.h>
#include <math.h>

#define B_    128
#define Q_    16
#define D_    1024
#define E_    300
#define K_    11
#define CTAS_PER_B 8
#define DOCS_PER_CTA (D_/CTAS_PER_B)   // 128
#define THREADS1 128
#define E4    (E_/4)                   // 75 float4
#define QSTRIDE 304                    // floats (76 f4)
#define SSTRIDE 136                    // mod 32 == 8 -> conflict-free 8-lane groups
#define PREF  5                        // prefetch batch (75 = 15*5)

// partials: [1024 CTAs][16 q][13] (11 kacc + 1 simacc + pad)
__device__ float g_part[B_*CTAS_PER_B*Q_*13];
__device__ int   g_count[B_];          // zero-init; reset by last CTA each run

__global__ __launch_bounds__(THREADS1, 7)
void knrm_part_kernel(const int* __restrict__ doctoks,
                      const int* __restrict__ querytoks,
                      const float* __restrict__ emb,
                      const float* __restrict__ mus,
                      const float* __restrict__ sigmas,
                      const float* __restrict__ fc_w,
                      const float* __restrict__ fc_b,
                      float* __restrict__ out)
{
    __shared__ float sm[Q_*QSTRIDE + 16];
    __shared__ int last_flag;
    float* qn    = sm;                // 16 x 304 ; later aliased as s_sh 16 x 136
    float* tmp16 = sm + Q_*QSTRIDE;

    const int tid = threadIdx.x;
    const int b   = blockIdx.x >> 3;
    const int cta = blockIdx.x & 7;

    // ---- load + normalize query embeddings into shared ----
    for (int i = tid; i < Q_*E_; i += THREADS1) {
        int q = i / E_, e = i - q*E_;
        int t = querytoks[b*Q_ + q];
        qn[q*QSTRIDE + e] = emb[t*E_ + e];
    }
    __syncthreads();
    {
        // 128 threads: 16 q-rows x 8 lanes each
        int q = tid >> 3, l = tid & 7;
        float ss = 0.f;
        for (int e = l; e < E_; e += 8) { float v = qn[q*QSTRIDE + e]; ss += v*v; }
        #pragma unroll
        for (int o = 4; o > 0; o >>= 1) ss += __shfl_down_sync(0xffffffffu, ss, o, 8);
        if (l == 0) tmp16[q] = 1.0f / (sqrtf(ss) + 1e-9f);
    }
    __syncthreads();
    for (int i = tid; i < Q_*E_; i += THREADS1) {
        int q = i / E_, e = i - q*E_;
        qn[q*QSTRIDE + e] *= tmp16[q];
    }
    __syncthreads();

    // ---- dot products: 1 doc/thread, MLP=5 batched loads ----
    const int t0 = doctoks[b*D_ + cta*DOCS_PER_CTA + tid];
    const float4* p0 = reinterpret_cast<const float4*>(emb) + (long)t0 * E4;
    const float4* qn4 = reinterpret_cast<const float4*>(qn);

    float acc[Q_];
    #pragma unroll
    for (int q = 0; q < Q_; q++) acc[q] = 0.f;
    float dd = 0.f;

    for (int base = 0; base < E4; base += PREF) {
        float4 buf[PREF];
        #pragma unroll
        for (int i = 0; i < PREF; i++) buf[i] = p0[base + i];
        #pragma unroll
        for (int i = 0; i < PREF; i++) {
            float4 a = buf[i];
            dd = fmaf(a.x,a.x, fmaf(a.y,a.y, fmaf(a.z,a.z, fmaf(a.w,a.w, dd))));
            #pragma unroll
            for (int q = 0; q < Q_; q++) {
                float4 v = qn4[q*(QSTRIDE/4) + base + i];
                acc[q] = fmaf(a.x,v.x, fmaf(a.y,v.y, fmaf(a.z,v.z, fmaf(a.w,v.w, acc[q]))));
            }
        }
    }

    const float inv = 1.0f / (sqrtf(dd) + 1e-9f);

    // ---- transpose s into shared (aliases dead qn region) ----
    float* s_sh = sm;   // 16 x 136
    __syncthreads();    // all qn reads done
    #pragma unroll
    for (int q = 0; q < Q_; q++)
        s_sh[q*SSTRIDE + tid] = acc[q] * inv;
    __syncthreads();

    // ---- RBF bank: 8 threads per q, each covers 16 docs ----
    const int myq = tid >> 3, myl = tid & 7;
    float mu_r[K_], w_r[K_];
    #pragma unroll
    for (int k = 0; k < K_; k++) {
        mu_r[k] = mus[k];
        float sg = sigmas[k];
        w_r[k] = -0.5f/(sg*sg);
    }
    float kacc[K_];
    #pragma unroll
    for (int k = 0; k < K_; k++) kacc[k] = 0.f;
    float simacc = 0.f;

    #pragma unroll 4
    for (int j = myl; j < DOCS_PER_CTA; j += 8) {
        float s = s_sh[myq*SSTRIDE + j];
        simacc += s;
        #pragma unroll
        for (int k = 0; k < K_; k++) {
            float dif = s - mu_r[k];
            kacc[k] += __expf(w_r[k]*dif*dif);
        }
    }

    // reduce over the 8 lanes of this q-group (contiguous lanes)
    #pragma unroll
    for (int k = 0; k < K_; k++) {
        float v = kacc[k];
        #pragma unroll
        for (int o = 4; o > 0; o >>= 1) v += __shfl_down_sync(0xffffffffu, v, o, 8);
        kacc[k] = v;
    }
    {
        float v = simacc;
        #pragma unroll
        for (int o = 4; o > 0; o >>= 1) v += __shfl_down_sync(0xffffffffu, v, o, 8);
        simacc = v;
    }
    if (myl == 0) {
        float* dst = &g_part[(blockIdx.x*Q_ + myq)*13];
        #pragma unroll
        for (int k = 0; k < K_; k++) dst[k] = kacc[k];
        dst[11] = simacc;
    }

    // ---- fused finalization: last CTA of this batch reduces + scores ----
    __syncthreads();
    if (tid == 0) {
        __threadfence();                       // release our partials
        int old = atomicAdd(&g_count[b], 1);
        last_flag = (old == CTAS_PER_B - 1);
    }
    __syncthreads();
    if (!last_flag) return;

    if (tid < 32) {
        __threadfence();                       // acquire other CTAs' partials
        const int lane = tid;
        const int q = lane & 15;               // lanes 16-31 duplicate; masked below
        const bool active = (lane < 16);

        float kb[K_];
        #pragma unroll
        for (int k = 0; k < K_; k++) kb[k] = 0.f;
        float sim = 0.f;
        #pragma unroll
        for (int cc = 0; cc < CTAS_PER_B; cc++) {
            const float* src = &g_part[((b*CTAS_PER_B + cc)*Q_ + q)*13];
            #pragma unroll
            for (int k = 0; k < K_; k++) kb[k] += src[k];
            sim += src[11];
        }
        const bool m = (sim != 0.0f) && active;
        float score = fc_b[0];
        #pragma unroll
        for (int k = 0; k < K_; k++) {
            float v = m ? logf(kb[k] + 1e-6f) : 0.0f;
            #pragma unroll
            for (int o = 8; o > 0; o >>= 1) v += __shfl_down_sync(0xffffffffu, v, o, 16);
            score = fmaf(v, fc_w[k], score);
        }
        if (lane == 0) {
            out[b] = score;
            g_count[b] = 0;                    // reset for next run / replay
        }
    }
}

extern "C" void kernel_launch(void* const* d_in, const int* in_sizes, int n_in,
                              void* d_out, int out_size)
{
    const int*   doctoks   = (const int*)  d_in[0];
    const int*   querytoks = (const int*)  d_in[1];
    // d_in[2] = query_idf (unused)
    const float* emb       = (const float*)d_in[3];
    const float* mus       = (const float*)d_in[4];
    const float* sigmas    = (const float*)d_in[5];
    const float* fc_w      = (const float*)d_in[6];
    const float* fc_b      = (const float*)d_in[7];
    float* out = (float*)d_out;

    knrm_part_kernel<<<B_*CTAS_PER_B, THREADS1>>>(
        doctoks, querytoks, emb, mus, sigmas, fc_w, fc_b, out);
}